// round 15
// baseline (speedup 1.0000x reference)
#include <cuda_runtime.h>
#include <cstdint>

#define NUM_BUCKETS  16384
#define HIDDEN       768
#define LN_EPS       1e-6f
#define WPB          8        // warps per block (256 threads)

__global__ __launch_bounds__(256, 5)
void canine_emb_ln_kernel(const int* __restrict__ ids,
                          const float* __restrict__ tables,
                          const float* __restrict__ ln_scale,
                          const float* __restrict__ ln_bias,
                          float* __restrict__ out,
                          int n_tokens)
{
    // Per-warp staging: 8 tokens x 768 floats = 24 KB.
    __shared__ __align__(128) float4 sbuf[WPB][HIDDEN / 4];

    const int wib  = threadIdx.x >> 5;               // warp in block
    const int warp = blockIdx.x * WPB + wib;         // token index
    const int lane = threadIdx.x & 31;

    if (warp < n_tokens) {
        // ids are int32 (JAX downcasts the declared int64). Broadcast load.
        const unsigned int h32 = (unsigned int)(__ldg(ids + warp) + 1);

        // Per-k compile-time tables (folded to immediates after full unroll).
        // f = lane + 32k spans at most 2 hash tables: h0 = floor(32k/24),
        // lane threshold TT = 24*(h0+1) - 32k. primes = {31,43,59,61,73,97,103,113}.
        const int      H0[6] = {0, 1, 2, 4, 5, 6};
        const int      TT[6] = {24, 16, 8, 24, 16, 8};
        const unsigned P0[6] = {31u, 43u, 59u, 73u, 97u, 103u};
        const unsigned P1[6] = {43u, 59u, 61u, 97u, 103u, 113u};

        const float4* t4 = reinterpret_cast<const float4*>(tables);

        // Single-pass gather (plain __ldg — evict_last refuted in R13),
        // hold the vectors, accumulate moments.
        float4 vec[6];
        float sum = 0.f, sumsq = 0.f;
#pragma unroll
        for (int k = 0; k < 6; k++) {
            const int f = lane + 32 * k;
            const int hi = (lane >= TT[k]) ? 1 : 0;      // compile-time threshold
            const int h = H0[k] + hi;
            const unsigned prime  = hi ? P1[k] : P0[k];  // SEL of immediates
            const unsigned bucket = (h32 * prime) & (NUM_BUCKETS - 1);
            const int idx = ((h << 14) | (int)bucket) * 24 + (f - 24 * h);
            const float4 x = __ldg(t4 + idx);
            vec[k] = x;
            sum   += x.x + x.y + x.z + x.w;
            sumsq += x.x * x.x + x.y * x.y + x.z * x.z + x.w * x.w;
        }

        // Warp reduction of moments.
#pragma unroll
        for (int o = 16; o > 0; o >>= 1) {
            sum   += __shfl_xor_sync(0xffffffffu, sum,   o);
            sumsq += __shfl_xor_sync(0xffffffffu, sumsq, o);
        }
        const float inv_n = 1.0f / (float)HIDDEN;
        const float mean  = sum * inv_n;
        const float var   = fmaxf(sumsq * inv_n - mean * mean, 0.0f);
        const float rstd  = rsqrtf(var + LN_EPS);

        const float4* sc = reinterpret_cast<const float4*>(ln_scale);
        const float4* bi = reinterpret_cast<const float4*>(ln_bias);

        // Normalize into shared staging buffer (conflict-free STS.128).
#pragma unroll
        for (int k = 0; k < 6; k++) {
            const int f = lane + 32 * k;
            const float4 s = __ldg(sc + f);   // 768 floats, always cache-hot
            const float4 b = __ldg(bi + f);
            const float4 x = vec[k];
            float4 r;
            r.x = fmaf((x.x - mean) * rstd, s.x, b.x);
            r.y = fmaf((x.y - mean) * rstd, s.y, b.y);
            r.z = fmaf((x.z - mean) * rstd, s.z, b.z);
            r.w = fmaf((x.w - mean) * rstd, s.w, b.w);
            sbuf[wib][f] = r;
        }

        __syncwarp();
        // Make the warp's shared writes visible to the async (TMA) proxy.
        asm volatile("fence.proxy.async.shared::cta;" ::: "memory");

        if (lane == 0) {
            // evict_first policy for the 201 MB output stream (R9 lesson:
            // keeping it out of the table's way in L2 is worth ~3.5 us).
            uint64_t pol;
            asm("createpolicy.fractional.L2::evict_first.b64 %0, 1.0;" : "=l"(pol));
            const unsigned saddr =
                (unsigned)__cvta_generic_to_shared(&sbuf[wib][0]);
            float* gdst = out + (size_t)warp * HIDDEN;
            // One dense 3 KB bulk store per token via the TMA engine:
            // writes land in L2 as contiguous blocks -> long DRAM write bursts.
            asm volatile(
                "cp.async.bulk.global.shared::cta.bulk_group.L2::cache_hint "
                "[%0], [%1], %2, %3;"
                :: "l"(gdst), "r"(saddr), "n"(HIDDEN * 4), "l"(pol)
                : "memory");
            asm volatile("cp.async.bulk.commit_group;" ::: "memory");
        }
    }

    // Drain this thread's bulk-store groups before exit (smem reuse + kernel
    // completion semantics). Lanes that issued nothing pass trivially.
    asm volatile("cp.async.bulk.wait_group 0;" ::: "memory");
}

extern "C" void kernel_launch(void* const* d_in, const int* in_sizes, int n_in,
                              void* d_out, int out_size)
{
    const int*   ids      = (const int*)d_in[0];     // [8, 8192] int32
    const float* tables   = (const float*)d_in[1];   // [8, 16384, 96] f32
    const float* ln_scale = (const float*)d_in[2];   // [768]
    const float* ln_bias  = (const float*)d_in[3];   // [768]
    float*       out      = (float*)d_out;           // [8, 8192, 768] f32

    const int n_tokens = in_sizes[0];                // 65536
    const int blocks = (n_tokens + WPB - 1) / WPB;   // 8192
    canine_emb_ln_kernel<<<blocks, WPB * 32>>>(
        ids, tables, ln_scale, ln_bias, out, n_tokens);
}

// round 17
// speedup vs baseline: 1.0745x; 1.0745x over previous
#include <cuda_runtime.h>
#include <cstdint>

#define NUM_BUCKETS  16384
#define HIDDEN       768
#define LN_EPS       1e-6f

__constant__ unsigned c_primes[8] = {31u, 43u, 59u, 61u, 73u, 97u, 103u, 113u};

__global__ __launch_bounds__(256, 5)
void canine_emb_ln_kernel(const int* __restrict__ ids,
                          const float* __restrict__ tables,
                          const float* __restrict__ ln_scale,
                          const float* __restrict__ ln_bias,
                          float* __restrict__ out,
                          int n_tokens)
{
    const int warp = (blockIdx.x * blockDim.x + threadIdx.x) >> 5;
    const int lane = threadIdx.x & 31;
    if (warp >= n_tokens) return;

    // ids are int32 (JAX downcasts the declared int64). Broadcast load.
    const unsigned h32 = (unsigned)(__ldg(ids + warp) + 1);

    // 256-bit granularity: token = 96 float8 chunks; row = 12 float8 (384 B,
    // 32B-aligned). Per lane: 3 chunks (e8 = lane + 32j). Halves every LSU
    // issue count vs the 128-bit version (3 LDG.256 vs 6 LDG.128, etc).
    float v[24];
    float sum = 0.f, sumsq = 0.f;
#pragma unroll
    for (int j = 0; j < 3; j++) {
        const int e8 = lane + 32 * j;          // float8 index [0,96)
        const int h  = e8 / 12;                // hash table [0,8)
        const int m  = e8 - 12 * h;            // float8 within row [0,12)
        const unsigned bucket = (h32 * c_primes[h]) & (NUM_BUCKETS - 1);
        const float* p = tables + (size_t)(((unsigned)h << 14) | bucket) * 96 + m * 8;
        unsigned g0, g1, g2, g3, g4, g5, g6, g7;
        asm("ld.global.nc.v8.b32 {%0,%1,%2,%3,%4,%5,%6,%7}, [%8];"
            : "=r"(g0), "=r"(g1), "=r"(g2), "=r"(g3),
              "=r"(g4), "=r"(g5), "=r"(g6), "=r"(g7)
            : "l"(p));
        const float f0 = __uint_as_float(g0), f1 = __uint_as_float(g1);
        const float f2 = __uint_as_float(g2), f3 = __uint_as_float(g3);
        const float f4 = __uint_as_float(g4), f5 = __uint_as_float(g5);
        const float f6 = __uint_as_float(g6), f7 = __uint_as_float(g7);
        v[j*8+0] = f0; v[j*8+1] = f1; v[j*8+2] = f2; v[j*8+3] = f3;
        v[j*8+4] = f4; v[j*8+5] = f5; v[j*8+6] = f6; v[j*8+7] = f7;
        sum   += ((f0 + f1) + (f2 + f3)) + ((f4 + f5) + (f6 + f7));
        sumsq += ((f0*f0 + f1*f1) + (f2*f2 + f3*f3))
               + ((f4*f4 + f5*f5) + (f6*f6 + f7*f7));
    }

    // Warp reduction of moments.
#pragma unroll
    for (int o = 16; o > 0; o >>= 1) {
        sum   += __shfl_xor_sync(0xffffffffu, sum,   o);
        sumsq += __shfl_xor_sync(0xffffffffu, sumsq, o);
    }
    const float inv_n = 1.0f / (float)HIDDEN;
    const float mean  = sum * inv_n;
    const float var   = fmaxf(sumsq * inv_n - mean * mean, 0.0f);
    const float rstd  = rsqrtf(var + LN_EPS);

    // evict_first policy for the 201 MB output stream (R9: keeping the
    // output out of the table's way in L2 is worth ~3.5 us).
    uint64_t pol;
    asm("createpolicy.fractional.L2::evict_first.b64 %0, 1.0;" : "=l"(pol));

    float* ob = out + (size_t)warp * HIDDEN;

#pragma unroll
    for (int j = 0; j < 3; j++) {
        const int e8 = lane + 32 * j;
        const float* sp = ln_scale + e8 * 8;
        const float* bp = ln_bias  + e8 * 8;
        unsigned s0,s1,s2,s3,s4,s5,s6,s7, b0,b1,b2,b3,b4,b5,b6,b7;
        asm("ld.global.nc.v8.b32 {%0,%1,%2,%3,%4,%5,%6,%7}, [%8];"
            : "=r"(s0),"=r"(s1),"=r"(s2),"=r"(s3),
              "=r"(s4),"=r"(s5),"=r"(s6),"=r"(s7) : "l"(sp));
        asm("ld.global.nc.v8.b32 {%0,%1,%2,%3,%4,%5,%6,%7}, [%8];"
            : "=r"(b0),"=r"(b1),"=r"(b2),"=r"(b3),
              "=r"(b4),"=r"(b5),"=r"(b6),"=r"(b7) : "l"(bp));
        unsigned r[8];
        const unsigned sv[8] = {s0,s1,s2,s3,s4,s5,s6,s7};
        const unsigned bv[8] = {b0,b1,b2,b3,b4,b5,b6,b7};
#pragma unroll
        for (int e = 0; e < 8; e++) {
            const float y = fmaf((v[j*8+e] - mean) * rstd,
                                 __uint_as_float(sv[e]),
                                 __uint_as_float(bv[e]));
            r[e] = __float_as_uint(y);
        }
        float* gp = ob + e8 * 8;
        asm volatile(
            "st.global.L2::cache_hint.v8.b32 [%0], {%1,%2,%3,%4,%5,%6,%7,%8}, %9;"
            :: "l"(gp),
               "r"(r[0]), "r"(r[1]), "r"(r[2]), "r"(r[3]),
               "r"(r[4]), "r"(r[5]), "r"(r[6]), "r"(r[7]),
               "l"(pol)
            : "memory");
    }
}

extern "C" void kernel_launch(void* const* d_in, const int* in_sizes, int n_in,
                              void* d_out, int out_size)
{
    const int*   ids      = (const int*)d_in[0];     // [8, 8192] int32
    const float* tables   = (const float*)d_in[1];   // [8, 16384, 96] f32
    const float* ln_scale = (const float*)d_in[2];   // [768]
    const float* ln_bias  = (const float*)d_in[3];   // [768]
    float*       out      = (float*)d_out;           // [8, 8192, 768] f32

    const int n_tokens = in_sizes[0];                // 65536
    const int warps_per_block = 8;                   // 256 threads
    const int blocks = (n_tokens + warps_per_block - 1) / warps_per_block;  // 8192
    canine_emb_ln_kernel<<<blocks, warps_per_block * 32>>>(
        ids, tables, ln_scale, ln_bias, out, n_tokens);
}